// round 15
// baseline (speedup 1.0000x reference)
#include <cuda_runtime.h>
#include <cuda_bf16.h>

// Problem constants
#define MM   1024
#define NN   2048
#define DVV  3
#define DCC  6
#define DD   8
#define BB   128
#define TT   5
#define CINC 48
#define VINV 25
#define VINP 28
#define HCC  192
#define HVV  100

#define PARTSZ ((size_t)MM * DCC * BB * DD)

typedef unsigned long long ull;
typedef unsigned int uint32;

// Messages (edge-major [edge][batch][8])
__device__ float g_cbuf[PARTSZ];                       // check->var
__device__ float g_vbuf[(size_t)NN * DVV * BB * DD];   // var->check

// var weights (prologue-prepared fp32)
__device__ float g_vw1t[(size_t)NN * HVV * VINP];
__device__ float g_vw2p[(size_t)NN * HVV * VINP];

// chk split-bf16 padded tiles (prologue-prepared; plain row-major, padded strides)
// W1T: per check [192 rows (hidden)][28 words (K=48 bf16 pairs + 4 pad)] -> 5376 words
// W2T: per check [48 rows (out)][100 words (K=192 pairs + 4 pad)]       -> 4800 words
__device__ __align__(16) uint32 g_w1hi[(size_t)MM * 5376];
__device__ __align__(16) uint32 g_w1lo[(size_t)MM * 5376];
__device__ __align__(16) uint32 g_w2hi[(size_t)MM * 4800];
__device__ __align__(16) uint32 g_w2lo[(size_t)MM * 4800];

// SMEM layout (bytes)
#define OFF_X_HI  0
#define OFF_X_LO  14336
#define OFF_H_HI  28672
#define OFF_H_LO  79872
#define OFF_W1HI  131072
#define OFF_W1LO  152576
#define OFF_W2HI  174080
#define OFF_W2LO  193280
#define OFF_B1    212480
#define OFF_B2    213248
#define OFF_SG    213440
#define CHK_SMEM  213984

// ---------------- helpers ----------------
__device__ __forceinline__ ull ffma2(ull a, ull b, ull c) {
    ull d; asm("fma.rn.f32x2 %0, %1, %2, %3;" : "=l"(d) : "l"(a), "l"(b), "l"(c)); return d;
}
__device__ __forceinline__ ull pack2(float lo, float hi) {
    ull d; asm("mov.b64 %0, {%1, %2};" : "=l"(d) : "f"(lo), "f"(hi)); return d;
}
__device__ __forceinline__ void unpack2(ull v, float& lo, float& hi) {
    asm("mov.b64 {%0, %1}, %2;" : "=f"(lo), "=f"(hi) : "l"(v));
}
__device__ __forceinline__ ull fadd2(ull a, ull b) {
    ull d; asm("add.rn.f32x2 %0, %1, %2;" : "=l"(d) : "l"(a), "l"(b)); return d;
}
__device__ __forceinline__ float gelu_fast(float v) {
    float x  = v * 0.70710678118654752f;
    float ax = fabsf(x);
    float t  = __fdividef(1.0f, fmaf(0.3275911f, ax, 1.0f));
    float e  = __expf(-ax * ax);
    float p  = fmaf(1.061405429f, t, -1.453152027f);
    p = fmaf(p, t, 1.421413741f);
    p = fmaf(p, t, -0.284496736f);
    p = fmaf(p, t, 0.254829592f);
    p = p * t;
    float r = fmaf(-p, e, 1.0f);
    r = copysignf(r, x);
    float hv = 0.5f * v;
    return fmaf(hv, r, hv);
}
__device__ __forceinline__ void split2(float v0, float v1, uint32& h2, uint32& l2) {
    __nv_bfloat16 h0 = __float2bfloat16(v0), h1 = __float2bfloat16(v1);
    float r0 = v0 - __bfloat162float(h0);
    float r1 = v1 - __bfloat162float(h1);
    __nv_bfloat16 l0 = __float2bfloat16(r0), l1 = __float2bfloat16(r1);
    h2 = (uint32)__bfloat16_as_ushort(h0) | ((uint32)__bfloat16_as_ushort(h1) << 16);
    l2 = (uint32)__bfloat16_as_ushort(l0) | ((uint32)__bfloat16_as_ushort(l1) << 16);
}
// mma.sync m16n8k16 row.col f32.bf16.bf16.f32, accumulate in place
__device__ __forceinline__ void mma16816(float* c, const uint32* a, uint32 b0, uint32 b1) {
    asm volatile("mma.sync.aligned.m16n8k16.row.col.f32.bf16.bf16.f32 "
        "{%0,%1,%2,%3}, {%4,%5,%6,%7}, {%8,%9}, {%0,%1,%2,%3};"
        : "+f"(c[0]), "+f"(c[1]), "+f"(c[2]), "+f"(c[3])
        : "r"(a[0]), "r"(a[1]), "r"(a[2]), "r"(a[3]), "r"(b0), "r"(b1));
}

// ---------------------------------------------------------------------------
// Prologue A: split chk weights to padded bf16 tiles.
// ---------------------------------------------------------------------------
extern "C" __global__ void __launch_bounds__(128)
chk_tile_prologue(const float* __restrict__ w1, const float* __restrict__ w2)
{
    const int m = blockIdx.x, tid = threadIdx.x;
    const float* w1g = w1 + (size_t)m * CINC * HCC;
    uint32* o1h = g_w1hi + (size_t)m * 5376;
    uint32* o1l = g_w1lo + (size_t)m * 5376;
    for (int p = tid; p < 5376; p += 128) {
        int n = p / 28, w = p - n * 28;
        int k0 = 2 * w, k1 = 2 * w + 1;
        float v0 = (k0 < CINC) ? w1g[k0 * HCC + n] : 0.0f;
        float v1 = (k1 < CINC) ? w1g[k1 * HCC + n] : 0.0f;
        uint32 h2, l2; split2(v0, v1, h2, l2);
        o1h[p] = h2; o1l[p] = l2;
    }
    const float* w2g = w2 + (size_t)m * HCC * CINC;
    uint32* o2h = g_w2hi + (size_t)m * 4800;
    uint32* o2l = g_w2lo + (size_t)m * 4800;
    for (int p = tid; p < 4800; p += 128) {
        int o = p / 100, w = p - o * 100;
        int j0 = 2 * w, j1 = 2 * w + 1;
        float v0 = (j0 < HCC) ? w2g[j0 * CINC + o] : 0.0f;
        float v1 = (j1 < HCC) ? w2g[j1 * CINC + o] : 0.0f;
        uint32 h2, l2; split2(v0, v1, h2, l2);
        o2h[p] = h2; o2l[p] = l2;
    }
}

// ---------------------------------------------------------------------------
// Prologue B: var weights (unchanged)
// ---------------------------------------------------------------------------
extern "C" __global__ void __launch_bounds__(128)
var_wt_prologue(const float* __restrict__ w1, const float* __restrict__ w2)
{
    __shared__ float sIn[VINV * 101];
    const int n = blockIdx.x, tid = threadIdx.x;
    const float* w1g = w1 + (size_t)n * VINV * HVV;
    const float* w2g = w2 + (size_t)n * HVV * VINV;
    for (int k = tid; k < VINV * HVV; k += 128) {
        int i = k / HVV, j = k - i * HVV;
        sIn[i * 101 + j] = w1g[k];
    }
    __syncthreads();
    float* o1 = g_vw1t + (size_t)n * HVV * VINP;
    float* o2 = g_vw2p + (size_t)n * HVV * VINP;
    for (int k = tid; k < HVV * VINP; k += 128) {
        int j = k / VINP, i = k - j * VINP;
        o1[k] = (i < VINV) ? sIn[i * 101 + j] : 0.0f;
        o2[k] = (i < VINV) ? w2g[j * VINV + i] : 0.0f;
    }
}

// ---------------------------------------------------------------------------
// Check kernel (mma.sync tensor path): one CTA per check, 128 threads (4 warps).
// Warp w owns batch rows [32w, 32w+32).  Split-bf16, 3 product terms.
// ---------------------------------------------------------------------------
extern "C" __global__ void __launch_bounds__(128)
chk_kernel(const float* __restrict__ b1, const float* __restrict__ b2,
           const int* __restrict__ synd, const float* __restrict__ prior,
           const int* __restrict__ chk_nbrs, const int* __restrict__ v2c,
           int first)
{
    extern __shared__ char smem[];
    uint32* sXh  = (uint32*)(smem + OFF_X_HI);
    uint32* sXl  = (uint32*)(smem + OFF_X_LO);
    uint32* sHh  = (uint32*)(smem + OFF_H_HI);
    uint32* sHl  = (uint32*)(smem + OFF_H_LO);
    uint32* sW1h = (uint32*)(smem + OFF_W1HI);
    uint32* sW1l = (uint32*)(smem + OFF_W1LO);
    uint32* sW2h = (uint32*)(smem + OFF_W2HI);
    uint32* sW2l = (uint32*)(smem + OFF_W2LO);
    float*  sB1  = (float*)(smem + OFF_B1);
    float*  sB2  = (float*)(smem + OFF_B2);
    float*  sSg  = (float*)(smem + OFF_SG);

    const int tid = threadIdx.x, m = blockIdx.x;
    const int wid = tid >> 5, lane = tid & 31;
    const int g = lane >> 2, t = lane & 3;

    // Stage weight tiles (straight 16B copies)
    {
        const uint4* s; uint4* d;
        s = (const uint4*)(g_w1hi + (size_t)m * 5376); d = (uint4*)sW1h;
        for (int k = tid; k < 1344; k += 128) d[k] = s[k];
        s = (const uint4*)(g_w1lo + (size_t)m * 5376); d = (uint4*)sW1l;
        for (int k = tid; k < 1344; k += 128) d[k] = s[k];
        s = (const uint4*)(g_w2hi + (size_t)m * 4800); d = (uint4*)sW2h;
        for (int k = tid; k < 1200; k += 128) d[k] = s[k];
        s = (const uint4*)(g_w2lo + (size_t)m * 4800); d = (uint4*)sW2l;
        for (int k = tid; k < 1200; k += 128) d[k] = s[k];
    }
    for (int k = tid; k < HCC; k += 128) sB1[k] = b1[(size_t)m * HCC + k];   // FIX: strided (HCC=192 > 128)
    if (tid < CINC) sB2[tid] = b2[(size_t)m * CINC + tid];
    sSg[tid] = 1.0f - 2.0f * (float)synd[(size_t)tid * MM + m];

    // Build X row (batch = tid): 48 msgs, split -> 24 words + 4 pad
    {
        float x[48];
        if (first) {
            #pragma unroll
            for (int k = 0; k < 48; ++k) x[k] = 0.0f;
            #pragma unroll
            for (int s = 0; s < DCC; ++s) {
                int idx = chk_nbrs[m * DCC + s];
                x[s * 8] = prior[idx];
            }
        } else {
            #pragma unroll
            for (int s = 0; s < DCC; ++s) {
                int idx = v2c[m * DCC + s];
                const float4* src = (const float4*)(g_vbuf + ((size_t)idx * BB + tid) * DD);
                float4 a = src[0], b = src[1];
                x[s*8+0]=a.x; x[s*8+1]=a.y; x[s*8+2]=a.z; x[s*8+3]=a.w;
                x[s*8+4]=b.x; x[s*8+5]=b.y; x[s*8+6]=b.z; x[s*8+7]=b.w;
            }
        }
        uint32* xh = sXh + tid * 28;
        uint32* xl = sXl + tid * 28;
        #pragma unroll
        for (int kp = 0; kp < 24; ++kp) {
            uint32 h2, l2; split2(x[2*kp], x[2*kp+1], h2, l2);
            xh[kp] = h2; xl[kp] = l2;
        }
        #pragma unroll
        for (int kp = 24; kp < 28; ++kp) { xh[kp] = 0; xl[kp] = 0; }
    }
    __syncthreads();

    const int r0 = wid * 32 + g;     // mt0 base row for this lane

    // ---- Layer 1: preload A fragments (X), 2 mtiles x 3 ksteps ----
    uint32 ah[2][3][4], al[2][3][4];
    #pragma unroll
    for (int mt = 0; mt < 2; ++mt) {
        int ra = r0 + mt * 16, rb = ra + 8;
        #pragma unroll
        for (int ks = 0; ks < 3; ++ks) {
            int w = ks * 8 + t;
            ah[mt][ks][0] = sXh[ra * 28 + w];
            ah[mt][ks][1] = sXh[rb * 28 + w];
            ah[mt][ks][2] = sXh[ra * 28 + w + 4];
            ah[mt][ks][3] = sXh[rb * 28 + w + 4];
            al[mt][ks][0] = sXl[ra * 28 + w];
            al[mt][ks][1] = sXl[rb * 28 + w];
            al[mt][ks][2] = sXl[ra * 28 + w + 4];
            al[mt][ks][3] = sXl[rb * 28 + w + 4];
        }
    }

    // ---- Layer 1 mainloop: N = 192 hidden, 24 n-tiles ----
    #pragma unroll 2
    for (int nt = 0; nt < 24; ++nt) {
        float acc0[4] = {0,0,0,0}, acc1[4] = {0,0,0,0};
        #pragma unroll
        for (int ks = 0; ks < 3; ++ks) {
            int bw = (nt * 8 + g) * 28 + ks * 8 + t;
            uint32 bh0 = sW1h[bw], bh1 = sW1h[bw + 4];
            uint32 bl0 = sW1l[bw], bl1 = sW1l[bw + 4];
            mma16816(acc0, ah[0][ks], bh0, bh1);
            mma16816(acc1, ah[1][ks], bh0, bh1);
            mma16816(acc0, ah[0][ks], bl0, bl1);
            mma16816(acc1, ah[1][ks], bl0, bl1);
            mma16816(acc0, al[0][ks], bh0, bh1);
            mma16816(acc1, al[1][ks], bh0, bh1);
        }
        // epilogue: +b1, gelu, split, store H (rows are warp-private)
        float bb0 = sB1[nt * 8 + 2 * t], bb1 = sB1[nt * 8 + 2 * t + 1];
        int hw = nt * 4 + t;
        {
            float v0 = gelu_fast(acc0[0] + bb0), v1 = gelu_fast(acc0[1] + bb1);
            uint32 h2, l2; split2(v0, v1, h2, l2);
            sHh[r0 * 100 + hw] = h2; sHl[r0 * 100 + hw] = l2;
            v0 = gelu_fast(acc0[2] + bb0); v1 = gelu_fast(acc0[3] + bb1);
            split2(v0, v1, h2, l2);
            sHh[(r0 + 8) * 100 + hw] = h2; sHl[(r0 + 8) * 100 + hw] = l2;
            v0 = gelu_fast(acc1[0] + bb0); v1 = gelu_fast(acc1[1] + bb1);
            split2(v0, v1, h2, l2);
            sHh[(r0 + 16) * 100 + hw] = h2; sHl[(r0 + 16) * 100 + hw] = l2;
            v0 = gelu_fast(acc1[2] + bb0); v1 = gelu_fast(acc1[3] + bb1);
            split2(v0, v1, h2, l2);
            sHh[(r0 + 24) * 100 + hw] = h2; sHl[(r0 + 24) * 100 + hw] = l2;
        }
    }
    __syncwarp();   // H rows are warp-private; warp-level visibility is enough

    // ---- Layer 2: K = 192 (12 ksteps, outer), N = 48 (6 n-tiles, acc resident) ----
    float acc[6][2][4];
    #pragma unroll
    for (int nt = 0; nt < 6; ++nt)
        #pragma unroll
        for (int mt = 0; mt < 2; ++mt)
            #pragma unroll
            for (int c = 0; c < 4; ++c) acc[nt][mt][c] = 0.0f;

    for (int ks = 0; ks < 12; ++ks) {
        uint32 a2h[2][4], a2l[2][4];
        int w = ks * 8 + t;
        #pragma unroll
        for (int mt = 0; mt < 2; ++mt) {
            int ra = r0 + mt * 16, rb = ra + 8;
            a2h[mt][0] = sHh[ra * 100 + w];
            a2h[mt][1] = sHh[rb * 100 + w];
            a2h[mt][2] = sHh[ra * 100 + w + 4];
            a2h[mt][3] = sHh[rb * 100 + w + 4];
            a2l[mt][0] = sHl[ra * 100 + w];
            a2l[mt][1] = sHl[rb * 100 + w];
            a2l[mt][2] = sHl[ra * 100 + w + 4];
            a2l[mt][3] = sHl[rb * 100 + w + 4];
        }
        #pragma unroll
        for (int nt = 0; nt < 6; ++nt) {
            int bw = (nt * 8 + g) * 100 + w;
            uint32 bh0 = sW2h[bw], bh1 = sW2h[bw + 4];
            uint32 bl0 = sW2l[bw], bl1 = sW2l[bw + 4];
            mma16816(acc[nt][0], a2h[0], bh0, bh1);
            mma16816(acc[nt][1], a2h[1], bh0, bh1);
            mma16816(acc[nt][0], a2h[0], bl0, bl1);
            mma16816(acc[nt][1], a2h[1], bl0, bl1);
            mma16816(acc[nt][0], a2l[0], bh0, bh1);
            mma16816(acc[nt][1], a2l[1], bh0, bh1);
        }
    }

    // ---- Epilogue 2: y = (acc + b2)*sg, write g_cbuf ----
    #pragma unroll
    for (int nt = 0; nt < 6; ++nt) {
        float b20 = sB2[nt * 8 + 2 * t], b21 = sB2[nt * 8 + 2 * t + 1];
        size_t ebase = (size_t)(m * DCC + nt) * BB;
        #pragma unroll
        for (int mt = 0; mt < 2; ++mt) {
            int ra = r0 + mt * 16, rb = ra + 8;
            float sga = sSg[ra], sgb = sSg[rb];
            float2 v;
            v.x = (acc[nt][mt][0] + b20) * sga;
            v.y = (acc[nt][mt][1] + b21) * sga;
            *(float2*)(g_cbuf + (ebase + ra) * DD + 2 * t) = v;
            v.x = (acc[nt][mt][2] + b20) * sgb;
            v.y = (acc[nt][mt][3] + b21) * sgb;
            *(float2*)(g_cbuf + (ebase + rb) * DD + 2 * t) = v;
        }
    }
}

// ---------------------------------------------------------------------------
// Var kernel (proven R5 config, single-buffer gather)
// ---------------------------------------------------------------------------
extern "C" __global__ void __launch_bounds__(64, 6)
var_kernel(const float* __restrict__ b1, const float* __restrict__ b2,
           const float* __restrict__ prior, const int* __restrict__ c2v,
           float* __restrict__ out_t)
{
    __shared__ __align__(16) float sW1T[HVV * VINP];
    __shared__ __align__(16) float sW2[HVV * VINP];
    __shared__ float sB1[HVV];
    __shared__ float sB2v[VINP];
    __shared__ int   sIdx[DVV];

    const int n = blockIdx.x, tid = threadIdx.x;
    const int b0 = tid, b1v = tid + 64;

    {
        const ulonglong2* src1 = (const ulonglong2*)(g_vw1t + (size_t)n * HVV * VINP);
        const ulonglong2* src2 = (const ulonglong2*)(g_vw2p + (size_t)n * HVV * VINP);
        ulonglong2* dst1 = (ulonglong2*)sW1T;
        ulonglong2* dst2 = (ulonglong2*)sW2;
        for (int k = tid; k < HVV * VINP / 4; k += 64) { dst1[k] = src1[k]; dst2[k] = src2[k]; }
    }
    for (int k = tid; k < HVV; k += 64) sB1[k] = b1[(size_t)n * HVV + k];
    if (tid < VINP) sB2v[tid] = (tid < VINV) ? b2[(size_t)n * VINV + tid] : 0.0f;
    if (tid < DVV)  sIdx[tid] = c2v[n * DVV + tid];
    __syncthreads();

    ull xu0[14], xu1[14];
    #pragma unroll
    for (int l = 0; l < DVV; ++l) {
        size_t base = (size_t)sIdx[l] * BB * DD;
        const ulonglong2* sA0 = (const ulonglong2*)(g_cbuf + base + (size_t)b0 * DD);
        ulonglong2 a0 = sA0[0], a1 = sA0[1];
        xu0[l*4+0] = a0.x; xu0[l*4+1] = a0.y; xu0[l*4+2] = a1.x; xu0[l*4+3] = a1.y;
        const ulonglong2* sA1 = (const ulonglong2*)(g_cbuf + base + (size_t)b1v * DD);
        ulonglong2 e0 = sA1[0], e1 = sA1[1];
        xu1[l*4+0] = e0.x; xu1[l*4+1] = e0.y; xu1[l*4+2] = e1.x; xu1[l*4+3] = e1.y;
    }
    {
        ull p = pack2(prior[n], 0.0f);
        xu0[12] = p; xu1[12] = p;
        xu0[13] = 0ULL; xu1[13] = 0ULL;
    }

    ull yu0[14], yu1[14];
    #pragma unroll
    for (int q = 0; q < 14; ++q) {
        ull b = pack2(sB2v[2*q], sB2v[2*q+1]);
        yu0[q] = b; yu1[q] = b;
    }

    #pragma unroll 2
    for (int j = 0; j < HVV; ++j) {
        const ulonglong2* wr = (const ulonglong2*)(sW1T + j * VINP);
        ull bj = pack2(sB1[j], 0.0f);
        ull a00 = bj, a01 = 0ULL, a10 = bj, a11 = 0ULL;
        #pragma unroll
        for (int q = 0; q < 7; ++q) {
            ulonglong2 w = wr[q];
            a00 = ffma2(xu0[2*q],   w.x, a00);
            a10 = ffma2(xu1[2*q],   w.x, a10);
            a01 = ffma2(xu0[2*q+1], w.y, a01);
            a11 = ffma2(xu1[2*q+1], w.y, a11);
        }
        float z0, z1, t0, t1;
        unpack2(fadd2(a00, a01), z0, t0);
        unpack2(fadd2(a10, a11), z1, t1);
        float h0 = gelu_fast(z0 + t0);
        float h1 = gelu_fast(z1 + t1);
        ull hh0 = pack2(h0, h0), hh1 = pack2(h1, h1);
        const ulonglong2* w2r = (const ulonglong2*)(sW2 + j * VINP);
        #pragma unroll
        for (int q = 0; q < 7; ++q) {
            ulonglong2 w = w2r[q];
            yu0[2*q]   = ffma2(hh0, w.x, yu0[2*q]);
            yu1[2*q]   = ffma2(hh1, w.x, yu1[2*q]);
            yu0[2*q+1] = ffma2(hh0, w.y, yu0[2*q+1]);
            yu1[2*q+1] = ffma2(hh1, w.y, yu1[2*q+1]);
        }
    }

    #pragma unroll
    for (int l = 0; l < DVV; ++l) {
        size_t base = (size_t)(n * DVV + l) * BB * DD;
        ulonglong2* d0 = (ulonglong2*)(g_vbuf + base + (size_t)b0 * DD);
        ulonglong2* d1 = (ulonglong2*)(g_vbuf + base + (size_t)b1v * DD);
        ulonglong2 o;
        o.x = yu0[l*4+0]; o.y = yu0[l*4+1]; d0[0] = o;
        o.x = yu0[l*4+2]; o.y = yu0[l*4+3]; d0[1] = o;
        o.x = yu1[l*4+0]; o.y = yu1[l*4+1]; d1[0] = o;
        o.x = yu1[l*4+2]; o.y = yu1[l*4+3]; d1[1] = o;
    }
    float lo, hi;
    unpack2(yu0[12], lo, hi); out_t[(size_t)b0  * NN + n] = lo;
    unpack2(yu1[12], lo, hi); out_t[(size_t)b1v * NN + n] = lo;
}

// ---------------------------------------------------------------------------
extern "C" void kernel_launch(void* const* d_in, const int* in_sizes, int n_in,
                              void* d_out, int out_size)
{
    const int*   synd  = (const int*)  d_in[0];
    const float* prior = (const float*)d_in[1];
    const float* cw1   = (const float*)d_in[2];
    const float* cb1   = (const float*)d_in[3];
    const float* cw2   = (const float*)d_in[4];
    const float* cb2   = (const float*)d_in[5];
    const float* vw1   = (const float*)d_in[6];
    const float* vb1   = (const float*)d_in[7];
    const float* vw2   = (const float*)d_in[8];
    const float* vb2   = (const float*)d_in[9];
    const int* chk_nbrs = (const int*)d_in[10];
    const int* c2v      = (const int*)d_in[11];
    const int* v2c      = (const int*)d_in[12];
    float* out = (float*)d_out;

    cudaFuncSetAttribute(chk_kernel, cudaFuncAttributeMaxDynamicSharedMemorySize, CHK_SMEM);

    chk_tile_prologue<<<MM, 128>>>(cw1, cw2);
    var_wt_prologue<<<NN, 128>>>(vw1, vw2);

    for (int t = 0; t < TT; ++t) {
        chk_kernel<<<MM, 128, CHK_SMEM>>>(cb1, cb2, synd, prior, chk_nbrs, v2c, (t == 0) ? 1 : 0);
        var_kernel<<<NN, 64>>>(vb1, vb2, prior, c2v, out + (size_t)t * BB * NN);
    }
}

// round 17
// speedup vs baseline: 1.8680x; 1.8680x over previous
#include <cuda_runtime.h>
#include <cuda_bf16.h>

// Problem constants
#define MM   1024
#define NN   2048
#define DVV  3
#define DCC  6
#define DD   8
#define BB   128
#define TT   5
#define CINC 48
#define VINV 25
#define VINP 28
#define HCC  192
#define HVV  100

#define PARTSZ ((size_t)MM * DCC * BB * DD)

typedef unsigned long long ull;
typedef unsigned int uint32;

// Messages (edge-major [edge][batch][8])
__device__ float g_cbuf[PARTSZ];                       // check->var
__device__ float g_vbuf[(size_t)NN * DVV * BB * DD];   // var->check

// var weights (prologue-prepared fp32)
__device__ float g_vw1t[(size_t)NN * HVV * VINP];
__device__ float g_vw2p[(size_t)NN * HVV * VINP];

// chk split-bf16 padded tiles (prologue-prepared)
// W1T: [192 rows][28 words] ; W2T: [48 rows][100 words]
__device__ __align__(16) uint32 g_w1hi[(size_t)MM * 5376];
__device__ __align__(16) uint32 g_w1lo[(size_t)MM * 5376];
__device__ __align__(16) uint32 g_w2hi[(size_t)MM * 4800];
__device__ __align__(16) uint32 g_w2lo[(size_t)MM * 4800];

// SMEM layout (bytes) — H tiles eliminated (kept in registers)
#define OFF_X_HI  0
#define OFF_X_LO  14336
#define OFF_W1HI  28672
#define OFF_W1LO  50176
#define OFF_W2HI  71680
#define OFF_W2LO  90880
#define OFF_B1    110080
#define OFF_B2    110848
#define OFF_SG    111040
#define CHK_SMEM  111584

// ---------------- helpers ----------------
__device__ __forceinline__ ull ffma2(ull a, ull b, ull c) {
    ull d; asm("fma.rn.f32x2 %0, %1, %2, %3;" : "=l"(d) : "l"(a), "l"(b), "l"(c)); return d;
}
__device__ __forceinline__ ull pack2(float lo, float hi) {
    ull d; asm("mov.b64 %0, {%1, %2};" : "=l"(d) : "f"(lo), "f"(hi)); return d;
}
__device__ __forceinline__ void unpack2(ull v, float& lo, float& hi) {
    asm("mov.b64 {%0, %1}, %2;" : "=f"(lo), "=f"(hi) : "l"(v));
}
__device__ __forceinline__ ull fadd2(ull a, ull b) {
    ull d; asm("add.rn.f32x2 %0, %1, %2;" : "=l"(d) : "l"(a), "l"(b)); return d;
}
__device__ __forceinline__ float gelu_fast(float v) {
    float x  = v * 0.70710678118654752f;
    float ax = fabsf(x);
    float t  = __fdividef(1.0f, fmaf(0.3275911f, ax, 1.0f));
    float e  = __expf(-ax * ax);
    float p  = fmaf(1.061405429f, t, -1.453152027f);
    p = fmaf(p, t, 1.421413741f);
    p = fmaf(p, t, -0.284496736f);
    p = fmaf(p, t, 0.254829592f);
    p = p * t;
    float r = fmaf(-p, e, 1.0f);
    r = copysignf(r, x);
    float hv = 0.5f * v;
    return fmaf(hv, r, hv);
}
__device__ __forceinline__ void split2(float v0, float v1, uint32& h2, uint32& l2) {
    __nv_bfloat16 h0 = __float2bfloat16(v0), h1 = __float2bfloat16(v1);
    float r0 = v0 - __bfloat162float(h0);
    float r1 = v1 - __bfloat162float(h1);
    __nv_bfloat16 l0 = __float2bfloat16(r0), l1 = __float2bfloat16(r1);
    h2 = (uint32)__bfloat16_as_ushort(h0) | ((uint32)__bfloat16_as_ushort(h1) << 16);
    l2 = (uint32)__bfloat16_as_ushort(l0) | ((uint32)__bfloat16_as_ushort(l1) << 16);
}
// mma.sync m16n8k16 row.col f32.bf16.bf16.f32, accumulate in place
__device__ __forceinline__ void mma16816(float* c, const uint32* a, uint32 b0, uint32 b1) {
    asm volatile("mma.sync.aligned.m16n8k16.row.col.f32.bf16.bf16.f32 "
        "{%0,%1,%2,%3}, {%4,%5,%6,%7}, {%8,%9}, {%0,%1,%2,%3};"
        : "+f"(c[0]), "+f"(c[1]), "+f"(c[2]), "+f"(c[3])
        : "r"(a[0]), "r"(a[1]), "r"(a[2]), "r"(a[3]), "r"(b0), "r"(b1));
}

// ---------------------------------------------------------------------------
// Prologue A: split chk weights to padded bf16 tiles.
// ---------------------------------------------------------------------------
extern "C" __global__ void __launch_bounds__(128)
chk_tile_prologue(const float* __restrict__ w1, const float* __restrict__ w2)
{
    const int m = blockIdx.x, tid = threadIdx.x;
    const float* w1g = w1 + (size_t)m * CINC * HCC;
    uint32* o1h = g_w1hi + (size_t)m * 5376;
    uint32* o1l = g_w1lo + (size_t)m * 5376;
    for (int p = tid; p < 5376; p += 128) {
        int n = p / 28, w = p - n * 28;
        int k0 = 2 * w, k1 = 2 * w + 1;
        float v0 = (k0 < CINC) ? w1g[k0 * HCC + n] : 0.0f;
        float v1 = (k1 < CINC) ? w1g[k1 * HCC + n] : 0.0f;
        uint32 h2, l2; split2(v0, v1, h2, l2);
        o1h[p] = h2; o1l[p] = l2;
    }
    const float* w2g = w2 + (size_t)m * HCC * CINC;
    uint32* o2h = g_w2hi + (size_t)m * 4800;
    uint32* o2l = g_w2lo + (size_t)m * 4800;
    for (int p = tid; p < 4800; p += 128) {
        int o = p / 100, w = p - o * 100;
        int j0 = 2 * w, j1 = 2 * w + 1;
        float v0 = (j0 < HCC) ? w2g[j0 * CINC + o] : 0.0f;
        float v1 = (j1 < HCC) ? w2g[j1 * CINC + o] : 0.0f;
        uint32 h2, l2; split2(v0, v1, h2, l2);
        o2h[p] = h2; o2l[p] = l2;
    }
}

// ---------------------------------------------------------------------------
// Prologue B: var weights (unchanged)
// ---------------------------------------------------------------------------
extern "C" __global__ void __launch_bounds__(128)
var_wt_prologue(const float* __restrict__ w1, const float* __restrict__ w2)
{
    __shared__ float sIn[VINV * 101];
    const int n = blockIdx.x, tid = threadIdx.x;
    const float* w1g = w1 + (size_t)n * VINV * HVV;
    const float* w2g = w2 + (size_t)n * HVV * VINV;
    for (int k = tid; k < VINV * HVV; k += 128) {
        int i = k / HVV, j = k - i * HVV;
        sIn[i * 101 + j] = w1g[k];
    }
    __syncthreads();
    float* o1 = g_vw1t + (size_t)n * HVV * VINP;
    float* o2 = g_vw2p + (size_t)n * HVV * VINP;
    for (int k = tid; k < HVV * VINP; k += 128) {
        int j = k / VINP, i = k - j * VINP;
        o1[k] = (i < VINV) ? sIn[i * 101 + j] : 0.0f;
        o2[k] = (i < VINV) ? w2g[j * VINV + i] : 0.0f;
    }
}

// ---------------------------------------------------------------------------
// Check kernel (fused-layer mma.sync): one CTA per check, 128 threads (4 warps).
// Per outer ks (12): layer-1 tiles nt=2ks,2ks+1 -> gelu -> registers -> layer-2.
// H never touches smem; smem = 111.5KB -> 2 CTAs/SM.
// ---------------------------------------------------------------------------
extern "C" __global__ void __launch_bounds__(128)
chk_kernel(const float* __restrict__ b1, const float* __restrict__ b2,
           const int* __restrict__ synd, const float* __restrict__ prior,
           const int* __restrict__ chk_nbrs, const int* __restrict__ v2c,
           int first)
{
    extern __shared__ char smem[];
    uint32* sXh  = (uint32*)(smem + OFF_X_HI);
    uint32* sXl  = (uint32*)(smem + OFF_X_LO);
    uint32* sW1h = (uint32*)(smem + OFF_W1HI);
    uint32* sW1l = (uint32*)(smem + OFF_W1LO);
    uint32* sW2h = (uint32*)(smem + OFF_W2HI);
    uint32* sW2l = (uint32*)(smem + OFF_W2LO);
    float*  sB1  = (float*)(smem + OFF_B1);
    float*  sB2  = (float*)(smem + OFF_B2);
    float*  sSg  = (float*)(smem + OFF_SG);

    const int tid = threadIdx.x, m = blockIdx.x;
    const int wid = tid >> 5, lane = tid & 31;
    const int g = lane >> 2, t = lane & 3;

    // Stage weight tiles
    {
        const uint4* s; uint4* d;
        s = (const uint4*)(g_w1hi + (size_t)m * 5376); d = (uint4*)sW1h;
        for (int k = tid; k < 1344; k += 128) d[k] = s[k];
        s = (const uint4*)(g_w1lo + (size_t)m * 5376); d = (uint4*)sW1l;
        for (int k = tid; k < 1344; k += 128) d[k] = s[k];
        s = (const uint4*)(g_w2hi + (size_t)m * 4800); d = (uint4*)sW2h;
        for (int k = tid; k < 1200; k += 128) d[k] = s[k];
        s = (const uint4*)(g_w2lo + (size_t)m * 4800); d = (uint4*)sW2l;
        for (int k = tid; k < 1200; k += 128) d[k] = s[k];
    }
    for (int k = tid; k < HCC; k += 128) sB1[k] = b1[(size_t)m * HCC + k];
    if (tid < CINC) sB2[tid] = b2[(size_t)m * CINC + tid];
    sSg[tid] = 1.0f - 2.0f * (float)synd[(size_t)tid * MM + m];

    // Build X row (batch = tid): 48 msgs -> split -> 24 words + 4 pad
    {
        float x[48];
        if (first) {
            #pragma unroll
            for (int k = 0; k < 48; ++k) x[k] = 0.0f;
            #pragma unroll
            for (int s = 0; s < DCC; ++s) {
                int idx = chk_nbrs[m * DCC + s];
                x[s * 8] = prior[idx];
            }
        } else {
            #pragma unroll
            for (int s = 0; s < DCC; ++s) {
                int idx = v2c[m * DCC + s];
                const float4* src = (const float4*)(g_vbuf + ((size_t)idx * BB + tid) * DD);
                float4 a = src[0], b = src[1];
                x[s*8+0]=a.x; x[s*8+1]=a.y; x[s*8+2]=a.z; x[s*8+3]=a.w;
                x[s*8+4]=b.x; x[s*8+5]=b.y; x[s*8+6]=b.z; x[s*8+7]=b.w;
            }
        }
        uint32* xh = sXh + tid * 28;
        uint32* xl = sXl + tid * 28;
        #pragma unroll
        for (int kp = 0; kp < 24; ++kp) {
            uint32 h2, l2; split2(x[2*kp], x[2*kp+1], h2, l2);
            xh[kp] = h2; xl[kp] = l2;
        }
        #pragma unroll
        for (int kp = 24; kp < 28; ++kp) { xh[kp] = 0; xl[kp] = 0; }
    }
    __syncthreads();

    const int r0 = wid * 32 + g;

    // Preload X A-fragments: 2 mtiles x 3 ksteps
    uint32 ah[2][3][4], al[2][3][4];
    #pragma unroll
    for (int mt = 0; mt < 2; ++mt) {
        int ra = r0 + mt * 16, rb = ra + 8;
        #pragma unroll
        for (int kk = 0; kk < 3; ++kk) {
            int w = kk * 8 + t;
            ah[mt][kk][0] = sXh[ra * 28 + w];
            ah[mt][kk][1] = sXh[rb * 28 + w];
            ah[mt][kk][2] = sXh[ra * 28 + w + 4];
            ah[mt][kk][3] = sXh[rb * 28 + w + 4];
            al[mt][kk][0] = sXl[ra * 28 + w];
            al[mt][kk][1] = sXl[rb * 28 + w];
            al[mt][kk][2] = sXl[ra * 28 + w + 4];
            al[mt][kk][3] = sXl[rb * 28 + w + 4];
        }
    }

    // Layer-2 resident accumulators
    float acc[6][2][4];
    #pragma unroll
    for (int nt = 0; nt < 6; ++nt)
        #pragma unroll
        for (int mt = 0; mt < 2; ++mt)
            #pragma unroll
            for (int c = 0; c < 4; ++c) acc[nt][mt][c] = 0.0f;

    // Fused mainloop over layer-2 ksteps
    for (int ks = 0; ks < 12; ++ks) {
        uint32 a2h[2][4], a2l[2][4];

        // Layer 1: tiles nt = 2ks, 2ks+1 -> gelu -> register H fragments
        #pragma unroll
        for (int hf = 0; hf < 2; ++hf) {
            int nt = 2 * ks + hf;
            float c0[4] = {0,0,0,0}, c1[4] = {0,0,0,0};
            #pragma unroll
            for (int kk = 0; kk < 3; ++kk) {
                int bw = (nt * 8 + g) * 28 + kk * 8 + t;
                uint32 bh0 = sW1h[bw], bh1 = sW1h[bw + 4];
                uint32 bl0 = sW1l[bw], bl1 = sW1l[bw + 4];
                mma16816(c0, ah[0][kk], bh0, bh1);
                mma16816(c1, ah[1][kk], bh0, bh1);
                mma16816(c0, ah[0][kk], bl0, bl1);
                mma16816(c1, ah[1][kk], bl0, bl1);
                mma16816(c0, al[0][kk], bh0, bh1);
                mma16816(c1, al[1][kk], bh0, bh1);
            }
            float bb0 = sB1[nt * 8 + 2 * t], bb1 = sB1[nt * 8 + 2 * t + 1];
            uint32 h2, l2;
            split2(gelu_fast(c0[0] + bb0), gelu_fast(c0[1] + bb1), h2, l2);
            a2h[0][hf * 2 + 0] = h2; a2l[0][hf * 2 + 0] = l2;
            split2(gelu_fast(c0[2] + bb0), gelu_fast(c0[3] + bb1), h2, l2);
            a2h[0][hf * 2 + 1] = h2; a2l[0][hf * 2 + 1] = l2;
            split2(gelu_fast(c1[0] + bb0), gelu_fast(c1[1] + bb1), h2, l2);
            a2h[1][hf * 2 + 0] = h2; a2l[1][hf * 2 + 0] = l2;
            split2(gelu_fast(c1[2] + bb0), gelu_fast(c1[3] + bb1), h2, l2);
            a2h[1][hf * 2 + 1] = h2; a2l[1][hf * 2 + 1] = l2;
        }
        // Wait — fragment word order: a2[.][0..1] must be words w (rows r,r+8),
        // a2[.][2..3] words w+4. hf=0 produced word ks*8+t -> slots 0,1;
        // hf=1 word ks*8+4+t -> slots 2,3. The mapping above places
        // hf0 -> slots {0,1} (rows r0,r0+8 / r0+16,r0+24) and hf1 -> {2,3}. BUT
        // slot semantics are a[0]=row r (w), a[1]=row r+8 (w), a[2]=row r (w+4),
        // a[3]=row r+8 (w+4): so hf0 fills a[0],a[1]; hf1 fills a[2],a[3]. The
        // index hf*2+{0,1} achieves exactly that ordering.

        // Layer 2: this kstep into resident accumulators
        int w = ks * 8 + t;
        #pragma unroll
        for (int nt = 0; nt < 6; ++nt) {
            int bw = (nt * 8 + g) * 100 + w;
            uint32 bh0 = sW2h[bw], bh1 = sW2h[bw + 4];
            uint32 bl0 = sW2l[bw], bl1 = sW2l[bw + 4];
            mma16816(acc[nt][0], a2h[0], bh0, bh1);
            mma16816(acc[nt][1], a2h[1], bh0, bh1);
            mma16816(acc[nt][0], a2h[0], bl0, bl1);
            mma16816(acc[nt][1], a2h[1], bl0, bl1);
            mma16816(acc[nt][0], a2l[0], bh0, bh1);
            mma16816(acc[nt][1], a2l[1], bh0, bh1);
        }
    }

    // Epilogue: y = (acc + b2)*sg, write g_cbuf
    #pragma unroll
    for (int nt = 0; nt < 6; ++nt) {
        float b20 = sB2[nt * 8 + 2 * t], b21 = sB2[nt * 8 + 2 * t + 1];
        size_t ebase = (size_t)(m * DCC + nt) * BB;
        #pragma unroll
        for (int mt = 0; mt < 2; ++mt) {
            int ra = r0 + mt * 16, rb = ra + 8;
            float sga = sSg[ra], sgb = sSg[rb];
            float2 v;
            v.x = (acc[nt][mt][0] + b20) * sga;
            v.y = (acc[nt][mt][1] + b21) * sga;
            *(float2*)(g_cbuf + (ebase + ra) * DD + 2 * t) = v;
            v.x = (acc[nt][mt][2] + b20) * sgb;
            v.y = (acc[nt][mt][3] + b21) * sgb;
            *(float2*)(g_cbuf + (ebase + rb) * DD + 2 * t) = v;
        }
    }
}

// ---------------------------------------------------------------------------
// Var kernel (proven R5 config, single-buffer gather)
// ---------------------------------------------------------------------------
extern "C" __global__ void __launch_bounds__(64, 6)
var_kernel(const float* __restrict__ b1, const float* __restrict__ b2,
           const float* __restrict__ prior, const int* __restrict__ c2v,
           float* __restrict__ out_t)
{
    __shared__ __align__(16) float sW1T[HVV * VINP];
    __shared__ __align__(16) float sW2[HVV * VINP];
    __shared__ float sB1[HVV];
    __shared__ float sB2v[VINP];
    __shared__ int   sIdx[DVV];

    const int n = blockIdx.x, tid = threadIdx.x;
    const int b0 = tid, b1v = tid + 64;

    {
        const ulonglong2* src1 = (const ulonglong2*)(g_vw1t + (size_t)n * HVV * VINP);
        const ulonglong2* src2 = (const ulonglong2*)(g_vw2p + (size_t)n * HVV * VINP);
        ulonglong2* dst1 = (ulonglong2*)sW1T;
        ulonglong2* dst2 = (ulonglong2*)sW2;
        for (int k = tid; k < HVV * VINP / 4; k += 64) { dst1[k] = src1[k]; dst2[k] = src2[k]; }
    }
    for (int k = tid; k < HVV; k += 64) sB1[k] = b1[(size_t)n * HVV + k];
    if (tid < VINP) sB2v[tid] = (tid < VINV) ? b2[(size_t)n * VINV + tid] : 0.0f;
    if (tid < DVV)  sIdx[tid] = c2v[n * DVV + tid];
    __syncthreads();

    ull xu0[14], xu1[14];
    #pragma unroll
    for (int l = 0; l < DVV; ++l) {
        size_t base = (size_t)sIdx[l] * BB * DD;
        const ulonglong2* sA0 = (const ulonglong2*)(g_cbuf + base + (size_t)b0 * DD);
        ulonglong2 a0 = sA0[0], a1 = sA0[1];
        xu0[l*4+0] = a0.x; xu0[l*4+1] = a0.y; xu0[l*4+2] = a1.x; xu0[l*4+3] = a1.y;
        const ulonglong2* sA1 = (const ulonglong2*)(g_cbuf + base + (size_t)b1v * DD);
        ulonglong2 e0 = sA1[0], e1 = sA1[1];
        xu1[l*4+0] = e0.x; xu1[l*4+1] = e0.y; xu1[l*4+2] = e1.x; xu1[l*4+3] = e1.y;
    }
    {
        ull p = pack2(prior[n], 0.0f);
        xu0[12] = p; xu1[12] = p;
        xu0[13] = 0ULL; xu1[13] = 0ULL;
    }

    ull yu0[14], yu1[14];
    #pragma unroll
    for (int q = 0; q < 14; ++q) {
        ull b = pack2(sB2v[2*q], sB2v[2*q+1]);
        yu0[q] = b; yu1[q] = b;
    }

    #pragma unroll 2
    for (int j = 0; j < HVV; ++j) {
        const ulonglong2* wr = (const ulonglong2*)(sW1T + j * VINP);
        ull bj = pack2(sB1[j], 0.0f);
        ull a00 = bj, a01 = 0ULL, a10 = bj, a11 = 0ULL;
        #pragma unroll
        for (int q = 0; q < 7; ++q) {
            ulonglong2 w = wr[q];
            a00 = ffma2(xu0[2*q],   w.x, a00);
            a10 = ffma2(xu1[2*q],   w.x, a10);
            a01 = ffma2(xu0[2*q+1], w.y, a01);
            a11 = ffma2(xu1[2*q+1], w.y, a11);
        }
        float z0, z1, t0, t1;
        unpack2(fadd2(a00, a01), z0, t0);
        unpack2(fadd2(a10, a11), z1, t1);
        float h0 = gelu_fast(z0 + t0);
        float h1 = gelu_fast(z1 + t1);
        ull hh0 = pack2(h0, h0), hh1 = pack2(h1, h1);
        const ulonglong2* w2r = (const ulonglong2*)(sW2 + j * VINP);
        #pragma unroll
        for (int q = 0; q < 7; ++q) {
            ulonglong2 w = w2r[q];
            yu0[2*q]   = ffma2(hh0, w.x, yu0[2*q]);
            yu1[2*q]   = ffma2(hh1, w.x, yu1[2*q]);
            yu0[2*q+1] = ffma2(hh0, w.y, yu0[2*q+1]);
            yu1[2*q+1] = ffma2(hh1, w.y, yu1[2*q+1]);
        }
    }

    #pragma unroll
    for (int l = 0; l < DVV; ++l) {
        size_t base = (size_t)(n * DVV + l) * BB * DD;
        ulonglong2* d0 = (ulonglong2*)(g_vbuf + base + (size_t)b0 * DD);
        ulonglong2* d1 = (ulonglong2*)(g_vbuf + base + (size_t)b1v * DD);
        ulonglong2 o;
        o.x = yu0[l*4+0]; o.y = yu0[l*4+1]; d0[0] = o;
        o.x = yu0[l*4+2]; o.y = yu0[l*4+3]; d0[1] = o;
        o.x = yu1[l*4+0]; o.y = yu1[l*4+1]; d1[0] = o;
        o.x = yu1[l*4+2]; o.y = yu1[l*4+3]; d1[1] = o;
    }
    float lo, hi;
    unpack2(yu0[12], lo, hi); out_t[(size_t)b0  * NN + n] = lo;
    unpack2(yu1[12], lo, hi); out_t[(size_t)b1v * NN + n] = lo;
}

// ---------------------------------------------------------------------------
extern "C" void kernel_launch(void* const* d_in, const int* in_sizes, int n_in,
                              void* d_out, int out_size)
{
    const int*   synd  = (const int*)  d_in[0];
    const float* prior = (const float*)d_in[1];
    const float* cw1   = (const float*)d_in[2];
    const float* cb1   = (const float*)d_in[3];
    const float* cw2   = (const float*)d_in[4];
    const float* cb2   = (const float*)d_in[5];
    const float* vw1   = (const float*)d_in[6];
    const float* vb1   = (const float*)d_in[7];
    const float* vw2   = (const float*)d_in[8];
    const float* vb2   = (const float*)d_in[9];
    const int* chk_nbrs = (const int*)d_in[10];
    const int* c2v      = (const int*)d_in[11];
    const int* v2c      = (const int*)d_in[12];
    float* out = (float*)d_out;

    cudaFuncSetAttribute(chk_kernel, cudaFuncAttributeMaxDynamicSharedMemorySize, CHK_SMEM);

    chk_tile_prologue<<<MM, 128>>>(cw1, cw2);
    var_wt_prologue<<<NN, 128>>>(vw1, vw2);

    for (int t = 0; t < TT; ++t) {
        chk_kernel<<<MM, 128, CHK_SMEM>>>(cb1, cb2, synd, prior, chk_nbrs, v2c, (t == 0) ? 1 : 0);
        var_kernel<<<NN, 64>>>(vb1, vb2, prior, c2v, out + (size_t)t * BB * NN);
    }
}